// round 6
// baseline (speedup 1.0000x reference)
#include <cuda_runtime.h>
#include <cuda_bf16.h>
#include <cstdint>

// x: (16, 64, 256, 256) fp32 = 16 Mi float4.  posIdx: 64 int32.
// out = posIdx[c] ? relu(x) : x
//
// Persistent grid-stride: 1184 CTAs (148 SMs x 8), each loops over tiles.
// Tile = 1024 contiguous vec4 (MLP=4 per thread, the measured knee).
// 16384 vec4/channel, 1024 | 16384 -> each tile is single-channel:
//   c = (tile >> 4) & 63
// Total tiles = 16777216 / 1024 = 16384; 16384 % 1184 != 0 -> loop w/ bound.

__global__ void __launch_bounds__(256) partial_relu_kernel(
    const float4* __restrict__ x,
    const int* __restrict__ posIdx,
    float4* __restrict__ out)
{
    const unsigned int ntiles = 16384u;
    for (unsigned int t = blockIdx.x; t < ntiles; t += gridDim.x) {
        const unsigned int base = t * 1024u + threadIdx.x;
        const bool m = posIdx[(t >> 4) & 63u] != 0;   // tile-uniform

        float4 v0 = __ldcs(&x[base]);
        float4 v1 = __ldcs(&x[base + 256u]);
        float4 v2 = __ldcs(&x[base + 512u]);
        float4 v3 = __ldcs(&x[base + 768u]);

        if (m) {
            v0.x = fmaxf(v0.x, 0.0f); v0.y = fmaxf(v0.y, 0.0f);
            v0.z = fmaxf(v0.z, 0.0f); v0.w = fmaxf(v0.w, 0.0f);
            v1.x = fmaxf(v1.x, 0.0f); v1.y = fmaxf(v1.y, 0.0f);
            v1.z = fmaxf(v1.z, 0.0f); v1.w = fmaxf(v1.w, 0.0f);
            v2.x = fmaxf(v2.x, 0.0f); v2.y = fmaxf(v2.y, 0.0f);
            v2.z = fmaxf(v2.z, 0.0f); v2.w = fmaxf(v2.w, 0.0f);
            v3.x = fmaxf(v3.x, 0.0f); v3.y = fmaxf(v3.y, 0.0f);
            v3.z = fmaxf(v3.z, 0.0f); v3.w = fmaxf(v3.w, 0.0f);
        }

        __stcs(&out[base],        v0);
        __stcs(&out[base + 256u], v1);
        __stcs(&out[base + 512u], v2);
        __stcs(&out[base + 768u], v3);
    }
}

extern "C" void kernel_launch(void* const* d_in, const int* in_sizes, int n_in,
                              void* d_out, int out_size)
{
    const float4* x = (const float4*)d_in[0];
    const int* posIdx = (const int*)d_in[1];
    float4* out = (float4*)d_out;

    // 148 SMs (152 on GB300; 148 keeps full waves on either) x 8 CTAs
    partial_relu_kernel<<<1184, 256>>>(x, posIdx, out);
}

// round 9
// speedup vs baseline: 1.0895x; 1.0895x over previous
#include <cuda_runtime.h>
#include <cuda_bf16.h>
#include <cstdint>

// x: (16, 64, 256, 256) fp32 = 16 Mi float4.  posIdx: 64 int32.
// out = posIdx[c] ? relu(x) : x
//
// Flat grid (no persistent loop — R6 showed loop-carried serialization hurts).
// Block covers 1024 contiguous vec4 (MLP=4/thread, the measured knee).
// 16384 vec4 per channel -> each block single-channel: c = (blockIdx.x>>4)&63.
// Loads: default caching. Stores: .cs (evict-first, streaming).

__global__ void __launch_bounds__(256) partial_relu_kernel(
    const float4* __restrict__ x,
    const int* __restrict__ posIdx,
    float4* __restrict__ out)
{
    const unsigned int base = blockIdx.x * 1024u + threadIdx.x;
    const bool m = posIdx[(blockIdx.x >> 4) & 63u] != 0;   // block-uniform

    float4 v0 = x[base];
    float4 v1 = x[base + 256u];
    float4 v2 = x[base + 512u];
    float4 v3 = x[base + 768u];

    if (m) {
        v0.x = fmaxf(v0.x, 0.0f); v0.y = fmaxf(v0.y, 0.0f);
        v0.z = fmaxf(v0.z, 0.0f); v0.w = fmaxf(v0.w, 0.0f);
        v1.x = fmaxf(v1.x, 0.0f); v1.y = fmaxf(v1.y, 0.0f);
        v1.z = fmaxf(v1.z, 0.0f); v1.w = fmaxf(v1.w, 0.0f);
        v2.x = fmaxf(v2.x, 0.0f); v2.y = fmaxf(v2.y, 0.0f);
        v2.z = fmaxf(v2.z, 0.0f); v2.w = fmaxf(v2.w, 0.0f);
        v3.x = fmaxf(v3.x, 0.0f); v3.y = fmaxf(v3.y, 0.0f);
        v3.z = fmaxf(v3.z, 0.0f); v3.w = fmaxf(v3.w, 0.0f);
    }

    __stcs(&out[base],        v0);
    __stcs(&out[base + 256u], v1);
    __stcs(&out[base + 512u], v2);
    __stcs(&out[base + 768u], v3);
}

extern "C" void kernel_launch(void* const* d_in, const int* in_sizes, int n_in,
                              void* d_out, int out_size)
{
    const float4* x = (const float4*)d_in[0];
    const int* posIdx = (const int*)d_in[1];
    float4* out = (float4*)d_out;

    // 16777216 vec4 / 1024 per block = 16384 blocks
    partial_relu_kernel<<<16384, 256>>>(x, posIdx, out);
}

// round 13
// speedup vs baseline: 1.0933x; 1.0035x over previous
#include <cuda_runtime.h>
#include <cuda_bf16.h>
#include <cstdint>

// x: (16, 64, 256, 256) fp32 = 16 Mi float4.  posIdx: 64 int32.
// out = posIdx[c] ? relu(x) : x
//
// FINAL (best measured config, R4: 81.8us harness / 73.9us ncu / 82.2% DRAM):
//  - flat grid 16384 CTAs x 256 thr (persistent loop regressed: R6)
//  - MLP=4 float4 per thread (measured knee: MLP1=78.5%, MLP4=82.2%, MLP8=81.9%)
//  - .cs evict-first on BOTH loads and stores (beats default loads: R9)
//  - block-uniform mask: 16384 vec4/channel, 1024 vec4/block ->
//      c = (blockIdx.x >> 4) & 63, single scalar load per block

__global__ void __launch_bounds__(256) partial_relu_kernel(
    const float4* __restrict__ x,
    const int* __restrict__ posIdx,
    float4* __restrict__ out)
{
    const unsigned int base = blockIdx.x * 1024u + threadIdx.x;
    const bool m = posIdx[(blockIdx.x >> 4) & 63u] != 0;   // uniform per block

    float4 v0 = __ldcs(&x[base]);
    float4 v1 = __ldcs(&x[base + 256u]);
    float4 v2 = __ldcs(&x[base + 512u]);
    float4 v3 = __ldcs(&x[base + 768u]);

    if (m) {
        v0.x = fmaxf(v0.x, 0.0f); v0.y = fmaxf(v0.y, 0.0f);
        v0.z = fmaxf(v0.z, 0.0f); v0.w = fmaxf(v0.w, 0.0f);
        v1.x = fmaxf(v1.x, 0.0f); v1.y = fmaxf(v1.y, 0.0f);
        v1.z = fmaxf(v1.z, 0.0f); v1.w = fmaxf(v1.w, 0.0f);
        v2.x = fmaxf(v2.x, 0.0f); v2.y = fmaxf(v2.y, 0.0f);
        v2.z = fmaxf(v2.z, 0.0f); v2.w = fmaxf(v2.w, 0.0f);
        v3.x = fmaxf(v3.x, 0.0f); v3.y = fmaxf(v3.y, 0.0f);
        v3.z = fmaxf(v3.z, 0.0f); v3.w = fmaxf(v3.w, 0.0f);
    }

    __stcs(&out[base],        v0);
    __stcs(&out[base + 256u], v1);
    __stcs(&out[base + 512u], v2);
    __stcs(&out[base + 768u], v3);
}

extern "C" void kernel_launch(void* const* d_in, const int* in_sizes, int n_in,
                              void* d_out, int out_size)
{
    const float4* x = (const float4*)d_in[0];
    const int* posIdx = (const int*)d_in[1];
    float4* out = (float4*)d_out;

    // 16777216 vec4 / 1024 per block = 16384 blocks
    partial_relu_kernel<<<16384, 256>>>(x, posIdx, out);
}